// round 12
// baseline (speedup 1.0000x reference)
#include <cuda_runtime.h>
#include <cuda_bf16.h>

#define N_NODES 100000
#define N_EDGES 1200000
#define N_GRAPHS 1000

#define EMB_BLOCKS ((N_NODES + 255) / 256)   // 391
#define SCAT_BLOCKS ((N_EDGES / 2 + 255) / 256)  // 2344 (2 edges/thread)
#define SCAN_BLOCKS 98                        // 98*8*128 = 100352 >= 100000

// ---------------- scratch (device globals; no allocation allowed) ----------
__device__ float g_h0[N_NODES * 32];
__device__ float g_agg1[N_NODES * 32];
__device__ float g_h1[N_NODES * 64];
__device__ float g_agg2[N_NODES * 64];

// zeroed-per-call block: [deg | cur | gdeg | scanpub | gsum]  (single memset)
#define ZERO_INTS (2 * N_NODES + N_GRAPHS + 128 + N_GRAPHS * 64)
__device__ int g_zero[ZERO_INTS];
#define G_DEG     (g_zero)
#define G_CUR     (g_zero + N_NODES)
#define G_GDEG    (g_zero + 2 * N_NODES)
#define G_SCANPUB (g_zero + 2 * N_NODES + N_GRAPHS)
#define G_GSUM    ((float*)(g_zero + 2 * N_NODES + N_GRAPHS + 128))

__device__ int g_off[N_NODES + 1];
__device__ int g_srcs[N_EDGES];
__device__ int g_goff[N_GRAPHS + 1];

// ---------------- packed f32x2 helpers (sm_103a) ----------------------------
__device__ __forceinline__ unsigned long long dup_f32(float a) {
    unsigned long long r;
    asm("mov.b64 %0, {%1, %1};" : "=l"(r) : "f"(a));
    return r;
}
__device__ __forceinline__ unsigned long long pack_f32(float lo, float hi) {
    unsigned long long r;
    asm("mov.b64 %0, {%1, %2};" : "=l"(r) : "f"(lo), "f"(hi));
    return r;
}
__device__ __forceinline__ void fma2(unsigned long long& d,
                                     unsigned long long a,
                                     unsigned long long b) {
    asm("fma.rn.f32x2 %0, %1, %2, %0;" : "+l"(d) : "l"(a), "l"(b));
}
__device__ __forceinline__ float2 unpack_f32(unsigned long long v) {
    float lo, hi;
    asm("mov.b64 {%0, %1}, %2;" : "=f"(lo), "=f"(hi) : "l"(v));
    return make_float2(lo, hi);
}
__device__ __forceinline__ void red_v4(float* p, float a, float b, float c, float d) {
    asm volatile("red.global.add.v4.f32 [%0], {%1,%2,%3,%4};"
                 :: "l"(p), "f"(a), "f"(b), "f"(c), "f"(d) : "memory");
}

// ---------------- K1: edge histogram (2 edges/thread) + graph histogram -----
__global__ void __launch_bounds__(256)
hist_kernel(const int* __restrict__ dst, const int* __restrict__ batch) {
    int t = blockIdx.x * blockDim.x + threadIdx.x;
    int e = t * 2;
    if (e < N_EDGES) {                 // N_EDGES even
        int2 d2 = *(const int2*)(dst + e);
        atomicAdd(&G_DEG[d2.x], 1);
        atomicAdd(&G_DEG[d2.y], 1);
    }
    if (t < N_NODES) atomicAdd(&G_GDEG[batch[t]], 1);
}

// ---------------- K2: single-kernel scans (decoupled lookback) --------------
__global__ void __launch_bounds__(256)
scan_all_kernel() {
    int b = blockIdx.x;
    int t = threadIdx.x;
    int w = t >> 5, lane = t & 31;

    if (b < SCAN_BLOCKS) {
        __shared__ int wsum[8];
        __shared__ int wred[8];
        __shared__ int sbase;

        int chunk = b * 8 + w;
        int idx = chunk * 128 + lane * 4;
        int4 v = make_int4(0, 0, 0, 0);
        if (idx < N_NODES) v = *(const int4*)(G_DEG + idx);
        int s = v.x + v.y + v.z + v.w;

        int tot = s;
#pragma unroll
        for (int off = 16; off > 0; off >>= 1)
            tot += __shfl_xor_sync(0xffffffffu, tot, off);
        if (lane == 0) wsum[w] = tot;
        __syncthreads();

        if (t == 0) {
            int bt = 0;
#pragma unroll
            for (int i = 0; i < 8; i++) bt += wsum[i];
            atomicExch(&G_SCANPUB[b], bt + 1);  // publish (value+1, 0 = not ready)
        }

        int my = 0;
        if (t < b) {
            int vv;
            do { vv = atomicAdd(&G_SCANPUB[t], 0); } while (vv == 0);
            my = vv - 1;
        }
#pragma unroll
        for (int off = 16; off > 0; off >>= 1)
            my += __shfl_xor_sync(0xffffffffu, my, off);
        if (lane == 0) wred[w] = my;
        __syncthreads();
        if (t == 0) {
            int bb = 0;
#pragma unroll
            for (int i = 0; i < 8; i++) bb += wred[i];
            sbase = bb;
        }
        __syncthreads();

        int base = sbase;
        for (int i = 0; i < w; i++) base += wsum[i];

        int incl = s;
#pragma unroll
        for (int off = 1; off < 32; off <<= 1) {
            int u = __shfl_up_sync(0xffffffffu, incl, off);
            if (lane >= off) incl += u;
        }
        int ebase = base + (incl - s);
        if (idx < N_NODES) {
            int4 o;
            o.x = ebase;
            o.y = ebase + v.x;
            o.z = o.y + v.y;
            o.w = o.z + v.z;
            *(int4*)(g_off + idx) = o;
            if (idx + 4 == N_NODES) g_off[N_NODES] = o.w + v.w;
        }
    } else {
        __shared__ int wt[8];
        int4 gv = make_int4(0, 0, 0, 0);
        if (t < 250) gv = *(const int4*)(G_GDEG + t * 4);
        int s = gv.x + gv.y + gv.z + gv.w;
        int incl = s;
#pragma unroll
        for (int off = 1; off < 32; off <<= 1) {
            int u = __shfl_up_sync(0xffffffffu, incl, off);
            if (lane >= off) incl += u;
        }
        if (lane == 31) wt[w] = incl;
        __syncthreads();
        int wbase = 0;
        for (int i = 0; i < w; i++) wbase += wt[i];
        int ebase = wbase + (incl - s);
        if (t < 250) {
            int4 o;
            o.x = ebase;
            o.y = ebase + gv.x;
            o.z = o.y + gv.y;
            o.w = o.z + gv.z;
            *(int4*)(g_goff + t * 4) = o;
            if (t == 249) g_goff[N_GRAPHS] = o.w + gv.w;
        }
    }
}

// ---------------- K3: fused scatter (CSR fill, 2 edges/thr) + embed MLP -----
// Scatter is L2-atomic-latency-bound; embed is FMA-bound — co-scheduled blocks
// overlap the two pipes.
__global__ void __launch_bounds__(256)
scatter_embed_kernel(const int* __restrict__ src,
                     const int* __restrict__ dst,
                     const int* __restrict__ x,
                     const float* __restrict__ shape_emb,
                     const float* __restrict__ color_emb,
                     const float* __restrict__ W_pre,
                     const float* __restrict__ b_pre) {
    __shared__ float sTab[128 + 64 + 512 + 32];
    if (blockIdx.x < EMB_BLOCKS) {
        float* sSE = sTab;
        float* sCE = sTab + 128;
        float* sW  = sTab + 192;
        float* sB  = sTab + 704;
        for (int idx = threadIdx.x; idx < 128; idx += 256) sSE[idx] = shape_emb[idx];
        for (int idx = threadIdx.x; idx < 64; idx += 256)  sCE[idx] = color_emb[idx];
        for (int idx = threadIdx.x; idx < 512; idx += 256) sW[idx]  = W_pre[idx];
        if (threadIdx.x < 32) sB[threadIdx.x] = b_pre[threadIdx.x];
        __syncthreads();

        int i = blockIdx.x * 256 + threadIdx.x;
        if (i >= N_NODES) return;
        int2 xi = ((const int2*)x)[i];
        float in[16];
#pragma unroll
        for (int k = 0; k < 8; k++) {
            in[k]     = sSE[xi.x * 8 + k];
            in[8 + k] = sCE[xi.y * 8 + k];
        }
        float out[32];
#pragma unroll
        for (int o = 0; o < 32; o++) {
            float acc = sB[o];
#pragma unroll
            for (int k = 0; k < 16; k++) acc += sW[o * 16 + k] * in[k];
            out[o] = fmaxf(acc, 0.0f);
        }
        float4* dstp = (float4*)(g_h0 + (long)i * 32);
#pragma unroll
        for (int j = 0; j < 8; j++)
            dstp[j] = make_float4(out[j * 4], out[j * 4 + 1], out[j * 4 + 2], out[j * 4 + 3]);
    } else {
        int e = ((blockIdx.x - EMB_BLOCKS) * 256 + threadIdx.x) * 2;
        if (e >= N_EDGES) return;   // N_EDGES even
        int2 d2 = *(const int2*)(dst + e);
        int2 s2 = *(const int2*)(src + e);
        int p0 = atomicAdd(&G_CUR[d2.x], 1);
        g_srcs[g_off[d2.x] + p0] = s2.x;
        int p1 = atomicAdd(&G_CUR[d2.y], 1);
        g_srcs[g_off[d2.y] + p1] = s2.y;
    }
}

// ---------------- CSR aggregation: 1 float4/thread, 4-edge unroll ------------
template <int D, int LOGP>
__global__ void __launch_bounds__(256)
csr_agg_kernel(const float* __restrict__ hin, float* __restrict__ agg) {
    constexpr int PARTS = 1 << LOGP;          // 8 (D=32) or 16 (D=64)
    int t = blockIdx.x * blockDim.x + threadIdx.x;
    int node = t >> LOGP;
    int part = t & (PARTS - 1);
    if (node >= N_NODES) return;
    int lo = g_off[node];
    int hi = g_off[node + 1];

    float4 a = make_float4(0.f, 0.f, 0.f, 0.f);

    const float4* base = (const float4*)hin + part;
    int e = lo;
    for (; e + 4 <= hi; e += 4) {
        int s0 = g_srcs[e];
        int s1 = g_srcs[e + 1];
        int s2 = g_srcs[e + 2];
        int s3 = g_srcs[e + 3];
        float4 u0 = base[(long)s0 * (D / 4)];
        float4 u1 = base[(long)s1 * (D / 4)];
        float4 u2 = base[(long)s2 * (D / 4)];
        float4 u3 = base[(long)s3 * (D / 4)];
        a.x += (u0.x + u1.x) + (u2.x + u3.x);
        a.y += (u0.y + u1.y) + (u2.y + u3.y);
        a.z += (u0.z + u1.z) + (u2.z + u3.z);
        a.w += (u0.w + u1.w) + (u2.w + u3.w);
    }
    for (; e < hi; e++) {
        int s = g_srcs[e];
        float4 u = base[(long)s * (D / 4)];
        a.x += u.x; a.y += u.y; a.z += u.z; a.w += u.w;
    }
    ((float4*)agg)[(long)node * (D / 4) + part] = a;
}

// ---------------- node update: agg@Wrel^T + b + h@Wroot^T, relu -------------
// POOL=true: reduce relu'd rows directly into G_GSUM[graph] (L2-resident)
template <int DIN, bool POOL>
__global__ void __launch_bounds__(128)
node_update_kernel(const float* __restrict__ agg,
                   const float* __restrict__ hin,
                   const float* __restrict__ Wrel,
                   const float* __restrict__ brel,
                   const float* __restrict__ Wroot,
                   float* __restrict__ hout,
                   const int* __restrict__ batch) {
    __shared__ float sWrel[DIN * 64];
    __shared__ float sWroot[DIN * 64];
    __shared__ float sB[64];
    for (int idx = threadIdx.x; idx < DIN * 64; idx += blockDim.x) {
        int o = idx & 63, k = idx >> 6;
        sWrel[idx]  = Wrel[o * DIN + k];
        sWroot[idx] = Wroot[o * DIN + k];
    }
    for (int idx = threadIdx.x; idx < 64; idx += blockDim.x) sB[idx] = brel[idx];
    __syncthreads();

    int t = blockIdx.x * blockDim.x + threadIdx.x;
    int quad = t >> 1;
    int part = t & 1;
    int n0 = quad * 4;
    if (n0 >= N_NODES) return;

    unsigned long long acc[4][16];
#pragma unroll
    for (int p = 0; p < 16; p++) {
        unsigned long long b2 = pack_f32(sB[part * 32 + p * 2], sB[part * 32 + p * 2 + 1]);
#pragma unroll
        for (int n = 0; n < 4; n++) acc[n][p] = b2;
    }

    const float4* aB = (const float4*)(agg + (long)n0 * DIN);
    const float4* hB = (const float4*)(hin + (long)n0 * DIN);
    constexpr int R4 = DIN / 4;

    for (int k4 = 0; k4 < DIN / 4; k4++) {
        float4 av[4], hv[4];
#pragma unroll
        for (int n = 0; n < 4; n++) {
            av[n] = aB[(long)n * R4 + k4];
            hv[n] = hB[(long)n * R4 + k4];
        }
#pragma unroll
        for (int kk = 0; kk < 4; kk++) {
            int k = k4 * 4 + kk;
            const unsigned long long* wr =
                (const unsigned long long*)(sWrel + k * 64 + part * 32);
            const unsigned long long* wo =
                (const unsigned long long*)(sWroot + k * 64 + part * 32);
            unsigned long long ad[4], hd[4];
#pragma unroll
            for (int n = 0; n < 4; n++) {
                float as = (kk == 0) ? av[n].x : (kk == 1) ? av[n].y : (kk == 2) ? av[n].z : av[n].w;
                float hs = (kk == 0) ? hv[n].x : (kk == 1) ? hv[n].y : (kk == 2) ? hv[n].z : hv[n].w;
                ad[n] = dup_f32(as);
                hd[n] = dup_f32(hs);
            }
#pragma unroll
            for (int p = 0; p < 16; p++) {
                unsigned long long w1 = wr[p];
                unsigned long long w2 = wo[p];
#pragma unroll
                for (int n = 0; n < 4; n++) {
                    fma2(acc[n][p], w1, ad[n]);
                    fma2(acc[n][p], w2, hd[n]);
                }
            }
        }
    }

#pragma unroll
    for (int n = 0; n < 4; n++) {
        float r[32];
#pragma unroll
        for (int j = 0; j < 16; j++) {
            float2 f = unpack_f32(acc[n][j]);
            r[j * 2]     = fmaxf(f.x, 0.f);
            r[j * 2 + 1] = fmaxf(f.y, 0.f);
        }
        if (POOL) {
            int g = batch[n0 + n];
            float* gp = G_GSUM + (long)g * 64 + part * 32;
#pragma unroll
            for (int q = 0; q < 8; q++)
                red_v4(gp + q * 4, r[q * 4], r[q * 4 + 1], r[q * 4 + 2], r[q * 4 + 3]);
        } else {
            float4* d = (float4*)(hout + (long)(n0 + n) * 64 + part * 32);
#pragma unroll
            for (int q = 0; q < 8; q++)
                d[q] = make_float4(r[q * 4], r[q * 4 + 1], r[q * 4 + 2], r[q * 4 + 3]);
        }
    }
}

// ---------------- final: mean + classifier (reads 256KB gsum) ----------------
__global__ void __launch_bounds__(64)
pool_cls_kernel(const float* __restrict__ W_cls,
                const float* __restrict__ b_cls,
                float* __restrict__ out) {
    __shared__ float sp[64];
    int g = blockIdx.x;
    int tid = threadIdx.x;
    float cnt = fmaxf((float)(g_goff[g + 1] - g_goff[g]), 1.0f);
    sp[tid] = G_GSUM[(long)g * 64 + tid] / cnt;
    __syncthreads();

    if (tid < 10) {
        float r = b_cls[tid];
#pragma unroll
        for (int k = 0; k < 64; k++) r += sp[k] * W_cls[tid * 64 + k];
        out[(long)g * 10 + tid] = r;
    }
}

// ---------------- launch ------------------------------------------------------
extern "C" void kernel_launch(void* const* d_in, const int* in_sizes, int n_in,
                              void* d_out, int out_size) {
    const int* x     = (const int*)d_in[0];
    const int* edge  = (const int*)d_in[1];
    const int* batch = (const int*)d_in[2];

    int se = -1;
    for (int i = 3; i < n_in; i++) {
        if (in_sizes[i] == 128) { se = i; break; }
    }
    if (se < 0) se = (n_in == 16) ? 4 : 3;

    const float* shape_emb = (const float*)d_in[se + 0];
    const float* color_emb = (const float*)d_in[se + 1];
    const float* W_pre     = (const float*)d_in[se + 2];
    const float* b_pre     = (const float*)d_in[se + 3];
    const float* W_rel1    = (const float*)d_in[se + 4];
    const float* b_rel1    = (const float*)d_in[se + 5];
    const float* W_root1   = (const float*)d_in[se + 6];
    const float* W_rel2    = (const float*)d_in[se + 7];
    const float* b_rel2    = (const float*)d_in[se + 8];
    const float* W_root2   = (const float*)d_in[se + 9];
    const float* W_cls     = (const float*)d_in[se + 10];
    const float* b_cls     = (const float*)d_in[se + 11];

    float* out = (float*)d_out;

    void *p_agg1, *p_agg2, *p_h0, *p_h1, *p_zero;
    cudaGetSymbolAddress(&p_agg1, g_agg1);
    cudaGetSymbolAddress(&p_agg2, g_agg2);
    cudaGetSymbolAddress(&p_h0, g_h0);
    cudaGetSymbolAddress(&p_h1, g_h1);
    cudaGetSymbolAddress(&p_zero, g_zero);

    cudaMemsetAsync(p_zero, 0, (size_t)ZERO_INTS * sizeof(int));

    const int* src = edge;
    const int* dstp = edge + N_EDGES;

    hist_kernel<<<(N_EDGES / 2 + 255) / 256, 256>>>(dstp, batch);

    scan_all_kernel<<<SCAN_BLOCKS + 1, 256>>>();

    scatter_embed_kernel<<<EMB_BLOCKS + SCAT_BLOCKS, 256>>>(
        src, dstp, x, shape_emb, color_emb, W_pre, b_pre);

    {
        long threads = (long)N_NODES * 8;   // PARTS=8 for D=32
        csr_agg_kernel<32, 3><<<(int)((threads + 255) / 256), 256>>>(
            (const float*)p_h0, (float*)p_agg1);
    }
    {
        int threads = (N_NODES / 4) * 2;
        node_update_kernel<32, false><<<(threads + 127) / 128, 128>>>(
            (const float*)p_agg1, (const float*)p_h0, W_rel1, b_rel1, W_root1,
            (float*)p_h1, batch);
    }
    {
        long threads = (long)N_NODES * 16;  // PARTS=16 for D=64
        csr_agg_kernel<64, 4><<<(int)((threads + 255) / 256), 256>>>(
            (const float*)p_h1, (float*)p_agg2);
    }
    {
        int threads = (N_NODES / 4) * 2;
        node_update_kernel<64, true><<<(threads + 127) / 128, 128>>>(
            (const float*)p_agg2, (const float*)p_h1, W_rel2, b_rel2, W_root2,
            nullptr, batch);
    }

    pool_cls_kernel<<<N_GRAPHS, 64>>>(W_cls, b_cls, out);

    (void)out_size;
}

// round 13
// speedup vs baseline: 1.0522x; 1.0522x over previous
#include <cuda_runtime.h>
#include <cuda_bf16.h>

#define N_NODES 100000
#define N_EDGES 1200000
#define N_GRAPHS 1000

#define EMB_BLOCKS ((N_NODES + 255) / 256)   // 391
#define SCAN_BLOCKS 98                        // 98*8*128 = 100352 >= 100000

// ---------------- scratch (device globals; no allocation allowed) ----------
__device__ __align__(16) __nv_bfloat16 g_h0[N_NODES * 32];   // bf16 activations
__device__ __align__(16) __nv_bfloat16 g_h1[N_NODES * 64];   // bf16 activations
__device__ float g_agg1[N_NODES * 32];                        // fp32 agg
__device__ float g_agg2[N_NODES * 64];                        // fp32 agg

// zeroed-per-call block: [deg | cur | gdeg | scanpub | gsum]  (single memset)
#define ZERO_INTS (2 * N_NODES + N_GRAPHS + 128 + N_GRAPHS * 64)
__device__ int g_zero[ZERO_INTS];
#define G_DEG     (g_zero)
#define G_CUR     (g_zero + N_NODES)
#define G_GDEG    (g_zero + 2 * N_NODES)
#define G_SCANPUB (g_zero + 2 * N_NODES + N_GRAPHS)
#define G_GSUM    ((float*)(g_zero + 2 * N_NODES + N_GRAPHS + 128))

__device__ int g_off[N_NODES + 1];
__device__ int g_srcs[N_EDGES];
__device__ int g_goff[N_GRAPHS + 1];

// ---------------- packed f32x2 / bf16 helpers (sm_103a) ---------------------
__device__ __forceinline__ unsigned long long dup_f32(float a) {
    unsigned long long r;
    asm("mov.b64 %0, {%1, %1};" : "=l"(r) : "f"(a));
    return r;
}
__device__ __forceinline__ unsigned long long pack_f32(float lo, float hi) {
    unsigned long long r;
    asm("mov.b64 %0, {%1, %2};" : "=l"(r) : "f"(lo), "f"(hi));
    return r;
}
__device__ __forceinline__ void fma2(unsigned long long& d,
                                     unsigned long long a,
                                     unsigned long long b) {
    asm("fma.rn.f32x2 %0, %1, %2, %0;" : "+l"(d) : "l"(a), "l"(b));
}
__device__ __forceinline__ float2 unpack_f32(unsigned long long v) {
    float lo, hi;
    asm("mov.b64 {%0, %1}, %2;" : "=f"(lo), "=f"(hi) : "l"(v));
    return make_float2(lo, hi);
}
__device__ __forceinline__ void red_v4(float* p, float a, float b, float c, float d) {
    asm volatile("red.global.add.v4.f32 [%0], {%1,%2,%3,%4};"
                 :: "l"(p), "f"(a), "f"(b), "f"(c), "f"(d) : "memory");
}
// bf16 (packed pair in u32) -> exact f32 expansion
__device__ __forceinline__ float bf_lo(unsigned u) { return __uint_as_float(u << 16); }
__device__ __forceinline__ float bf_hi(unsigned u) { return __uint_as_float(u & 0xffff0000u); }
__device__ __forceinline__ unsigned bf_pack(float lo, float hi) {
    __nv_bfloat162 b = __float22bfloat162_rn(make_float2(lo, hi));
    return *(unsigned*)&b;
}

// ---------------- K1: edge hist + (embed+pre MLP (bf16 out) + graph hist) ---
__global__ void __launch_bounds__(256)
hist_embed_kernel(const int* __restrict__ dst,
                  const int* __restrict__ batch,
                  const int* __restrict__ x,
                  const float* __restrict__ shape_emb,
                  const float* __restrict__ color_emb,
                  const float* __restrict__ W_pre,
                  const float* __restrict__ b_pre) {
    __shared__ float sTab[128 + 64 + 512 + 32];
    if (blockIdx.x < EMB_BLOCKS) {
        float* sSE = sTab;
        float* sCE = sTab + 128;
        float* sW  = sTab + 192;
        float* sB  = sTab + 704;
        for (int idx = threadIdx.x; idx < 128; idx += 256) sSE[idx] = shape_emb[idx];
        for (int idx = threadIdx.x; idx < 64; idx += 256)  sCE[idx] = color_emb[idx];
        for (int idx = threadIdx.x; idx < 512; idx += 256) sW[idx]  = W_pre[idx];
        if (threadIdx.x < 32) sB[threadIdx.x] = b_pre[threadIdx.x];
        __syncthreads();

        int i = blockIdx.x * 256 + threadIdx.x;
        if (i >= N_NODES) return;
        atomicAdd(&G_GDEG[batch[i]], 1);
        int2 xi = ((const int2*)x)[i];
        float in[16];
#pragma unroll
        for (int k = 0; k < 8; k++) {
            in[k]     = sSE[xi.x * 8 + k];
            in[8 + k] = sCE[xi.y * 8 + k];
        }
        float out[32];
#pragma unroll
        for (int o = 0; o < 32; o++) {
            float acc = sB[o];
#pragma unroll
            for (int k = 0; k < 16; k++) acc += sW[o * 16 + k] * in[k];
            out[o] = fmaxf(acc, 0.0f);
        }
        unsigned w[16];
#pragma unroll
        for (int j = 0; j < 16; j++) w[j] = bf_pack(out[j * 2], out[j * 2 + 1]);
        uint4* dstp = (uint4*)(g_h0 + (long)i * 32);
#pragma unroll
        for (int q = 0; q < 4; q++)
            dstp[q] = make_uint4(w[q * 4], w[q * 4 + 1], w[q * 4 + 2], w[q * 4 + 3]);
    } else {
        int e = (blockIdx.x - EMB_BLOCKS) * 256 + threadIdx.x;
        if (e >= N_EDGES) return;
        atomicAdd(&G_DEG[dst[e]], 1);
    }
}

// ---------------- K2: single-kernel scans (decoupled lookback) --------------
__global__ void __launch_bounds__(256)
scan_all_kernel() {
    int b = blockIdx.x;
    int t = threadIdx.x;
    int w = t >> 5, lane = t & 31;

    if (b < SCAN_BLOCKS) {
        __shared__ int wsum[8];
        __shared__ int wred[8];
        __shared__ int sbase;

        int chunk = b * 8 + w;
        int idx = chunk * 128 + lane * 4;
        int4 v = make_int4(0, 0, 0, 0);
        if (idx < N_NODES) v = *(const int4*)(G_DEG + idx);
        int s = v.x + v.y + v.z + v.w;

        int tot = s;
#pragma unroll
        for (int off = 16; off > 0; off >>= 1)
            tot += __shfl_xor_sync(0xffffffffu, tot, off);
        if (lane == 0) wsum[w] = tot;
        __syncthreads();

        if (t == 0) {
            int bt = 0;
#pragma unroll
            for (int i = 0; i < 8; i++) bt += wsum[i];
            atomicExch(&G_SCANPUB[b], bt + 1);  // publish (value+1, 0 = not ready)
        }

        int my = 0;
        if (t < b) {
            int vv;
            do { vv = atomicAdd(&G_SCANPUB[t], 0); } while (vv == 0);
            my = vv - 1;
        }
#pragma unroll
        for (int off = 16; off > 0; off >>= 1)
            my += __shfl_xor_sync(0xffffffffu, my, off);
        if (lane == 0) wred[w] = my;
        __syncthreads();
        if (t == 0) {
            int bb = 0;
#pragma unroll
            for (int i = 0; i < 8; i++) bb += wred[i];
            sbase = bb;
        }
        __syncthreads();

        int base = sbase;
        for (int i = 0; i < w; i++) base += wsum[i];

        int incl = s;
#pragma unroll
        for (int off = 1; off < 32; off <<= 1) {
            int u = __shfl_up_sync(0xffffffffu, incl, off);
            if (lane >= off) incl += u;
        }
        int ebase = base + (incl - s);
        if (idx < N_NODES) {
            int4 o;
            o.x = ebase;
            o.y = ebase + v.x;
            o.z = o.y + v.y;
            o.w = o.z + v.z;
            *(int4*)(g_off + idx) = o;
            if (idx + 4 == N_NODES) g_off[N_NODES] = o.w + v.w;
        }
    } else {
        __shared__ int wt[8];
        int4 gv = make_int4(0, 0, 0, 0);
        if (t < 250) gv = *(const int4*)(G_GDEG + t * 4);
        int s = gv.x + gv.y + gv.z + gv.w;
        int incl = s;
#pragma unroll
        for (int off = 1; off < 32; off <<= 1) {
            int u = __shfl_up_sync(0xffffffffu, incl, off);
            if (lane >= off) incl += u;
        }
        if (lane == 31) wt[w] = incl;
        __syncthreads();
        int wbase = 0;
        for (int i = 0; i < w; i++) wbase += wt[i];
        int ebase = wbase + (incl - s);
        if (t < 250) {
            int4 o;
            o.x = ebase;
            o.y = ebase + gv.x;
            o.z = o.y + gv.y;
            o.w = o.z + gv.z;
            *(int4*)(g_goff + t * 4) = o;
            if (t == 249) g_goff[N_GRAPHS] = o.w + gv.w;
        }
    }
}

// ---------------- K3: scatter (CSR fill), 2 edges/thread ---------------------
__global__ void __launch_bounds__(256)
scatter_kernel(const int* __restrict__ src, const int* __restrict__ dst) {
    int e = (blockIdx.x * blockDim.x + threadIdx.x) * 2;
    if (e >= N_EDGES) return;   // N_EDGES even
    int2 d2 = *(const int2*)(dst + e);
    int2 s2 = *(const int2*)(src + e);
    int p0 = atomicAdd(&G_CUR[d2.x], 1);
    g_srcs[g_off[d2.x] + p0] = s2.x;
    int p1 = atomicAdd(&G_CUR[d2.y], 1);
    g_srcs[g_off[d2.y] + p1] = s2.y;
}

// ---------------- CSR aggregation (bf16 in, fp32 out), 4-edge unroll ---------
// Thread owns one uint4 = 8 bf16 of its node's row. PARTS = D/8.
template <int D, int LOGP>
__global__ void __launch_bounds__(256)
csr_agg_kernel(const __nv_bfloat16* __restrict__ hin, float* __restrict__ agg) {
    constexpr int PARTS = 1 << LOGP;          // 4 (D=32) or 8 (D=64)
    int t = blockIdx.x * blockDim.x + threadIdx.x;
    int node = t >> LOGP;
    int part = t & (PARTS - 1);
    if (node >= N_NODES) return;
    int lo = g_off[node];
    int hi = g_off[node + 1];

    float a[8];
#pragma unroll
    for (int j = 0; j < 8; j++) a[j] = 0.0f;

    const uint4* base = (const uint4*)hin + part;  // row = PARTS uint4
    int e = lo;
    for (; e + 4 <= hi; e += 4) {
        int s0 = g_srcs[e];
        int s1 = g_srcs[e + 1];
        int s2 = g_srcs[e + 2];
        int s3 = g_srcs[e + 3];
        uint4 u0 = base[(long)s0 * PARTS];
        uint4 u1 = base[(long)s1 * PARTS];
        uint4 u2 = base[(long)s2 * PARTS];
        uint4 u3 = base[(long)s3 * PARTS];
        a[0] += (bf_lo(u0.x) + bf_lo(u1.x)) + (bf_lo(u2.x) + bf_lo(u3.x));
        a[1] += (bf_hi(u0.x) + bf_hi(u1.x)) + (bf_hi(u2.x) + bf_hi(u3.x));
        a[2] += (bf_lo(u0.y) + bf_lo(u1.y)) + (bf_lo(u2.y) + bf_lo(u3.y));
        a[3] += (bf_hi(u0.y) + bf_hi(u1.y)) + (bf_hi(u2.y) + bf_hi(u3.y));
        a[4] += (bf_lo(u0.z) + bf_lo(u1.z)) + (bf_lo(u2.z) + bf_lo(u3.z));
        a[5] += (bf_hi(u0.z) + bf_hi(u1.z)) + (bf_hi(u2.z) + bf_hi(u3.z));
        a[6] += (bf_lo(u0.w) + bf_lo(u1.w)) + (bf_lo(u2.w) + bf_lo(u3.w));
        a[7] += (bf_hi(u0.w) + bf_hi(u1.w)) + (bf_hi(u2.w) + bf_hi(u3.w));
    }
    for (; e < hi; e++) {
        int s = g_srcs[e];
        uint4 u = base[(long)s * PARTS];
        a[0] += bf_lo(u.x); a[1] += bf_hi(u.x);
        a[2] += bf_lo(u.y); a[3] += bf_hi(u.y);
        a[4] += bf_lo(u.z); a[5] += bf_hi(u.z);
        a[6] += bf_lo(u.w); a[7] += bf_hi(u.w);
    }
    float4* out = (float4*)agg + (long)node * (D / 4) + part * 2;
    out[0] = make_float4(a[0], a[1], a[2], a[3]);
    out[1] = make_float4(a[4], a[5], a[6], a[7]);
}

// ---------------- node update: agg(fp32)@Wrel^T + b + h(bf16)@Wroot^T, relu -
// POOL=true: reduce relu'd rows into G_GSUM[graph]; else write bf16 h rows.
template <int DIN, bool POOL>
__global__ void __launch_bounds__(128)
node_update_kernel(const float* __restrict__ agg,
                   const __nv_bfloat16* __restrict__ hin,
                   const float* __restrict__ Wrel,
                   const float* __restrict__ brel,
                   const float* __restrict__ Wroot,
                   __nv_bfloat16* __restrict__ hout,
                   const int* __restrict__ batch) {
    __shared__ float sWrel[DIN * 64];
    __shared__ float sWroot[DIN * 64];
    __shared__ float sB[64];
    for (int idx = threadIdx.x; idx < DIN * 64; idx += blockDim.x) {
        int o = idx & 63, k = idx >> 6;
        sWrel[idx]  = Wrel[o * DIN + k];
        sWroot[idx] = Wroot[o * DIN + k];
    }
    for (int idx = threadIdx.x; idx < 64; idx += blockDim.x) sB[idx] = brel[idx];
    __syncthreads();

    int t = blockIdx.x * blockDim.x + threadIdx.x;
    int quad = t >> 1;
    int part = t & 1;
    int n0 = quad * 4;
    if (n0 >= N_NODES) return;

    unsigned long long acc[4][16];
#pragma unroll
    for (int p = 0; p < 16; p++) {
        unsigned long long b2 = pack_f32(sB[part * 32 + p * 2], sB[part * 32 + p * 2 + 1]);
#pragma unroll
        for (int n = 0; n < 4; n++) acc[n][p] = b2;
    }

    const float4* aB = (const float4*)(agg + (long)n0 * DIN);
    const uint2* hB = (const uint2*)(hin + (long)n0 * DIN);  // uint2 = 4 bf16
    constexpr int R4 = DIN / 4;

    for (int k4 = 0; k4 < DIN / 4; k4++) {
        float4 av[4], hv[4];
#pragma unroll
        for (int n = 0; n < 4; n++) {
            av[n] = aB[(long)n * R4 + k4];
            uint2 hu = hB[(long)n * R4 + k4];
            hv[n] = make_float4(bf_lo(hu.x), bf_hi(hu.x), bf_lo(hu.y), bf_hi(hu.y));
        }
#pragma unroll
        for (int kk = 0; kk < 4; kk++) {
            int k = k4 * 4 + kk;
            const unsigned long long* wr =
                (const unsigned long long*)(sWrel + k * 64 + part * 32);
            const unsigned long long* wo =
                (const unsigned long long*)(sWroot + k * 64 + part * 32);
            unsigned long long ad[4], hd[4];
#pragma unroll
            for (int n = 0; n < 4; n++) {
                float as = (kk == 0) ? av[n].x : (kk == 1) ? av[n].y : (kk == 2) ? av[n].z : av[n].w;
                float hs = (kk == 0) ? hv[n].x : (kk == 1) ? hv[n].y : (kk == 2) ? hv[n].z : hv[n].w;
                ad[n] = dup_f32(as);
                hd[n] = dup_f32(hs);
            }
#pragma unroll
            for (int p = 0; p < 16; p++) {
                unsigned long long w1 = wr[p];
                unsigned long long w2 = wo[p];
#pragma unroll
                for (int n = 0; n < 4; n++) {
                    fma2(acc[n][p], w1, ad[n]);
                    fma2(acc[n][p], w2, hd[n]);
                }
            }
        }
    }

#pragma unroll
    for (int n = 0; n < 4; n++) {
        float r[32];
#pragma unroll
        for (int j = 0; j < 16; j++) {
            float2 f = unpack_f32(acc[n][j]);
            r[j * 2]     = fmaxf(f.x, 0.f);
            r[j * 2 + 1] = fmaxf(f.y, 0.f);
        }
        if (POOL) {
            int g = batch[n0 + n];
            float* gp = G_GSUM + (long)g * 64 + part * 32;
#pragma unroll
            for (int q = 0; q < 8; q++)
                red_v4(gp + q * 4, r[q * 4], r[q * 4 + 1], r[q * 4 + 2], r[q * 4 + 3]);
        } else {
            unsigned w[16];
#pragma unroll
            for (int j = 0; j < 16; j++) w[j] = bf_pack(r[j * 2], r[j * 2 + 1]);
            uint4* d = (uint4*)(hout + (long)(n0 + n) * 64 + part * 32);
#pragma unroll
            for (int q = 0; q < 4; q++)
                d[q] = make_uint4(w[q * 4], w[q * 4 + 1], w[q * 4 + 2], w[q * 4 + 3]);
        }
    }
}

// ---------------- final: mean + classifier (reads 256KB gsum) ----------------
__global__ void __launch_bounds__(64)
pool_cls_kernel(const float* __restrict__ W_cls,
                const float* __restrict__ b_cls,
                float* __restrict__ out) {
    __shared__ float sp[64];
    int g = blockIdx.x;
    int tid = threadIdx.x;
    float cnt = fmaxf((float)(g_goff[g + 1] - g_goff[g]), 1.0f);
    sp[tid] = G_GSUM[(long)g * 64 + tid] / cnt;
    __syncthreads();

    if (tid < 10) {
        float r = b_cls[tid];
#pragma unroll
        for (int k = 0; k < 64; k++) r += sp[k] * W_cls[tid * 64 + k];
        out[(long)g * 10 + tid] = r;
    }
}

// ---------------- launch ------------------------------------------------------
extern "C" void kernel_launch(void* const* d_in, const int* in_sizes, int n_in,
                              void* d_out, int out_size) {
    const int* x     = (const int*)d_in[0];
    const int* edge  = (const int*)d_in[1];
    const int* batch = (const int*)d_in[2];

    int se = -1;
    for (int i = 3; i < n_in; i++) {
        if (in_sizes[i] == 128) { se = i; break; }
    }
    if (se < 0) se = (n_in == 16) ? 4 : 3;

    const float* shape_emb = (const float*)d_in[se + 0];
    const float* color_emb = (const float*)d_in[se + 1];
    const float* W_pre     = (const float*)d_in[se + 2];
    const float* b_pre     = (const float*)d_in[se + 3];
    const float* W_rel1    = (const float*)d_in[se + 4];
    const float* b_rel1    = (const float*)d_in[se + 5];
    const float* W_root1   = (const float*)d_in[se + 6];
    const float* W_rel2    = (const float*)d_in[se + 7];
    const float* b_rel2    = (const float*)d_in[se + 8];
    const float* W_root2   = (const float*)d_in[se + 9];
    const float* W_cls     = (const float*)d_in[se + 10];
    const float* b_cls     = (const float*)d_in[se + 11];

    float* out = (float*)d_out;

    void *p_agg1, *p_agg2, *p_h0, *p_h1, *p_zero;
    cudaGetSymbolAddress(&p_agg1, g_agg1);
    cudaGetSymbolAddress(&p_agg2, g_agg2);
    cudaGetSymbolAddress(&p_h0, g_h0);
    cudaGetSymbolAddress(&p_h1, g_h1);
    cudaGetSymbolAddress(&p_zero, g_zero);

    cudaMemsetAsync(p_zero, 0, (size_t)ZERO_INTS * sizeof(int));

    const int* src = edge;
    const int* dstp = edge + N_EDGES;

    hist_embed_kernel<<<EMB_BLOCKS + (N_EDGES + 255) / 256, 256>>>(
        dstp, batch, x, shape_emb, color_emb, W_pre, b_pre);

    scan_all_kernel<<<SCAN_BLOCKS + 1, 256>>>();

    scatter_kernel<<<(N_EDGES / 2 + 255) / 256, 256>>>(src, dstp);

    {
        long threads = (long)N_NODES * 4;   // PARTS=4 for D=32 (8 bf16/thread)
        csr_agg_kernel<32, 2><<<(int)((threads + 255) / 256), 256>>>(
            (const __nv_bfloat16*)p_h0, (float*)p_agg1);
    }
    {
        int threads = (N_NODES / 4) * 2;
        node_update_kernel<32, false><<<(threads + 127) / 128, 128>>>(
            (const float*)p_agg1, (const __nv_bfloat16*)p_h0, W_rel1, b_rel1, W_root1,
            (__nv_bfloat16*)p_h1, batch);
    }
    {
        long threads = (long)N_NODES * 8;   // PARTS=8 for D=64 (8 bf16/thread)
        csr_agg_kernel<64, 3><<<(int)((threads + 255) / 256), 256>>>(
            (const __nv_bfloat16*)p_h1, (float*)p_agg2);
    }
    {
        int threads = (N_NODES / 4) * 2;
        node_update_kernel<64, true><<<(threads + 127) / 128, 128>>>(
            (const float*)p_agg2, (const __nv_bfloat16*)p_h1, W_rel2, b_rel2, W_root2,
            nullptr, batch);
    }

    pool_cls_kernel<<<N_GRAPHS, 64>>>(W_cls, b_cls, out);

    (void)out_size;
}

// round 14
// speedup vs baseline: 1.0669x; 1.0140x over previous
#include <cuda_runtime.h>
#include <cuda_bf16.h>

#define N_NODES 100000
#define N_EDGES 1200000
#define N_GRAPHS 1000

#define EMB_BLOCKS ((N_NODES + 255) / 256)   // 391
#define SCAN_BLOCKS 98                        // 98*8*128 = 100352 >= 100000

// PDL grid-dependency controls (sm_90+)
#define GDC_LAUNCH() asm volatile("griddepcontrol.launch_dependents;")
#define GDC_WAIT()   asm volatile("griddepcontrol.wait;" ::: "memory")

// ---------------- scratch (device globals; no allocation allowed) ----------
__device__ __align__(16) __nv_bfloat16 g_h0[N_NODES * 32];   // bf16 activations
__device__ __align__(16) __nv_bfloat16 g_h1[N_NODES * 64];   // bf16 activations
__device__ float g_agg1[N_NODES * 32];                        // fp32 agg
__device__ float g_agg2[N_NODES * 64];                        // fp32 agg

// zeroed-per-call block: [deg | cur | gdeg | scanpub | gsum]  (single memset)
#define ZERO_INTS (2 * N_NODES + N_GRAPHS + 128 + N_GRAPHS * 64)
__device__ int g_zero[ZERO_INTS];
#define G_DEG     (g_zero)
#define G_CUR     (g_zero + N_NODES)
#define G_GDEG    (g_zero + 2 * N_NODES)
#define G_SCANPUB (g_zero + 2 * N_NODES + N_GRAPHS)
#define G_GSUM    ((float*)(g_zero + 2 * N_NODES + N_GRAPHS + 128))

__device__ int g_off[N_NODES + 1];
__device__ int g_srcs[N_EDGES];
__device__ int g_goff[N_GRAPHS + 1];

// ---------------- packed f32x2 / bf16 helpers (sm_103a) ---------------------
__device__ __forceinline__ unsigned long long dup_f32(float a) {
    unsigned long long r;
    asm("mov.b64 %0, {%1, %1};" : "=l"(r) : "f"(a));
    return r;
}
__device__ __forceinline__ unsigned long long pack_f32(float lo, float hi) {
    unsigned long long r;
    asm("mov.b64 %0, {%1, %2};" : "=l"(r) : "f"(lo), "f"(hi));
    return r;
}
__device__ __forceinline__ void fma2(unsigned long long& d,
                                     unsigned long long a,
                                     unsigned long long b) {
    asm("fma.rn.f32x2 %0, %1, %2, %0;" : "+l"(d) : "l"(a), "l"(b));
}
__device__ __forceinline__ float2 unpack_f32(unsigned long long v) {
    float lo, hi;
    asm("mov.b64 {%0, %1}, %2;" : "=f"(lo), "=f"(hi) : "l"(v));
    return make_float2(lo, hi);
}
__device__ __forceinline__ void red_v4(float* p, float a, float b, float c, float d) {
    asm volatile("red.global.add.v4.f32 [%0], {%1,%2,%3,%4};"
                 :: "l"(p), "f"(a), "f"(b), "f"(c), "f"(d) : "memory");
}
// bf16 (packed pair in u32) -> exact f32 expansion
__device__ __forceinline__ float bf_lo(unsigned u) { return __uint_as_float(u << 16); }
__device__ __forceinline__ float bf_hi(unsigned u) { return __uint_as_float(u & 0xffff0000u); }
__device__ __forceinline__ unsigned bf_pack(float lo, float hi) {
    __nv_bfloat162 b = __float22bfloat162_rn(make_float2(lo, hi));
    return *(unsigned*)&b;
}

// ---------------- K1: edge hist + (embed+pre MLP (bf16 out) + graph hist) ---
__global__ void __launch_bounds__(256)
hist_embed_kernel(const int* __restrict__ dst,
                  const int* __restrict__ batch,
                  const int* __restrict__ x,
                  const float* __restrict__ shape_emb,
                  const float* __restrict__ color_emb,
                  const float* __restrict__ W_pre,
                  const float* __restrict__ b_pre) {
    GDC_LAUNCH();
    __shared__ float sTab[128 + 64 + 512 + 32];
    if (blockIdx.x < EMB_BLOCKS) {
        float* sSE = sTab;
        float* sCE = sTab + 128;
        float* sW  = sTab + 192;
        float* sB  = sTab + 704;
        for (int idx = threadIdx.x; idx < 128; idx += 256) sSE[idx] = shape_emb[idx];
        for (int idx = threadIdx.x; idx < 64; idx += 256)  sCE[idx] = color_emb[idx];
        for (int idx = threadIdx.x; idx < 512; idx += 256) sW[idx]  = W_pre[idx];
        if (threadIdx.x < 32) sB[threadIdx.x] = b_pre[threadIdx.x];
        __syncthreads();

        int i = blockIdx.x * 256 + threadIdx.x;
        if (i >= N_NODES) return;
        atomicAdd(&G_GDEG[batch[i]], 1);
        int2 xi = ((const int2*)x)[i];
        float in[16];
#pragma unroll
        for (int k = 0; k < 8; k++) {
            in[k]     = sSE[xi.x * 8 + k];
            in[8 + k] = sCE[xi.y * 8 + k];
        }
        float out[32];
#pragma unroll
        for (int o = 0; o < 32; o++) {
            float acc = sB[o];
#pragma unroll
            for (int k = 0; k < 16; k++) acc += sW[o * 16 + k] * in[k];
            out[o] = fmaxf(acc, 0.0f);
        }
        unsigned w[16];
#pragma unroll
        for (int j = 0; j < 16; j++) w[j] = bf_pack(out[j * 2], out[j * 2 + 1]);
        uint4* dstp = (uint4*)(g_h0 + (long)i * 32);
#pragma unroll
        for (int q = 0; q < 4; q++)
            dstp[q] = make_uint4(w[q * 4], w[q * 4 + 1], w[q * 4 + 2], w[q * 4 + 3]);
    } else {
        int e = (blockIdx.x - EMB_BLOCKS) * 256 + threadIdx.x;
        if (e >= N_EDGES) return;
        atomicAdd(&G_DEG[dst[e]], 1);
    }
}

// ---------------- K2: single-kernel scans (decoupled lookback) --------------
__global__ void __launch_bounds__(256)
scan_all_kernel() {
    GDC_LAUNCH();
    GDC_WAIT();   // G_DEG / G_GDEG from hist_embed
    int b = blockIdx.x;
    int t = threadIdx.x;
    int w = t >> 5, lane = t & 31;

    if (b < SCAN_BLOCKS) {
        __shared__ int wsum[8];
        __shared__ int wred[8];
        __shared__ int sbase;

        int chunk = b * 8 + w;
        int idx = chunk * 128 + lane * 4;
        int4 v = make_int4(0, 0, 0, 0);
        if (idx < N_NODES) v = *(const int4*)(G_DEG + idx);
        int s = v.x + v.y + v.z + v.w;

        int tot = s;
#pragma unroll
        for (int off = 16; off > 0; off >>= 1)
            tot += __shfl_xor_sync(0xffffffffu, tot, off);
        if (lane == 0) wsum[w] = tot;
        __syncthreads();

        if (t == 0) {
            int bt = 0;
#pragma unroll
            for (int i = 0; i < 8; i++) bt += wsum[i];
            atomicExch(&G_SCANPUB[b], bt + 1);  // publish (value+1, 0 = not ready)
        }

        int my = 0;
        if (t < b) {
            int vv;
            do { vv = atomicAdd(&G_SCANPUB[t], 0); } while (vv == 0);
            my = vv - 1;
        }
#pragma unroll
        for (int off = 16; off > 0; off >>= 1)
            my += __shfl_xor_sync(0xffffffffu, my, off);
        if (lane == 0) wred[w] = my;
        __syncthreads();
        if (t == 0) {
            int bb = 0;
#pragma unroll
            for (int i = 0; i < 8; i++) bb += wred[i];
            sbase = bb;
        }
        __syncthreads();

        int base = sbase;
        for (int i = 0; i < w; i++) base += wsum[i];

        int incl = s;
#pragma unroll
        for (int off = 1; off < 32; off <<= 1) {
            int u = __shfl_up_sync(0xffffffffu, incl, off);
            if (lane >= off) incl += u;
        }
        int ebase = base + (incl - s);
        if (idx < N_NODES) {
            int4 o;
            o.x = ebase;
            o.y = ebase + v.x;
            o.z = o.y + v.y;
            o.w = o.z + v.z;
            *(int4*)(g_off + idx) = o;
            if (idx + 4 == N_NODES) g_off[N_NODES] = o.w + v.w;
        }
    } else {
        __shared__ int wt[8];
        int4 gv = make_int4(0, 0, 0, 0);
        if (t < 250) gv = *(const int4*)(G_GDEG + t * 4);
        int s = gv.x + gv.y + gv.z + gv.w;
        int incl = s;
#pragma unroll
        for (int off = 1; off < 32; off <<= 1) {
            int u = __shfl_up_sync(0xffffffffu, incl, off);
            if (lane >= off) incl += u;
        }
        if (lane == 31) wt[w] = incl;
        __syncthreads();
        int wbase = 0;
        for (int i = 0; i < w; i++) wbase += wt[i];
        int ebase = wbase + (incl - s);
        if (t < 250) {
            int4 o;
            o.x = ebase;
            o.y = ebase + gv.x;
            o.z = o.y + gv.y;
            o.w = o.z + gv.z;
            *(int4*)(g_goff + t * 4) = o;
            if (t == 249) g_goff[N_GRAPHS] = o.w + gv.w;
        }
    }
}

// ---------------- K3: scatter (CSR fill), 2 edges/thread ---------------------
__global__ void __launch_bounds__(256)
scatter_kernel(const int* __restrict__ src, const int* __restrict__ dst) {
    GDC_LAUNCH();
    GDC_WAIT();   // g_off from scan
    int e = (blockIdx.x * blockDim.x + threadIdx.x) * 2;
    if (e >= N_EDGES) return;   // N_EDGES even
    int2 d2 = *(const int2*)(dst + e);
    int2 s2 = *(const int2*)(src + e);
    int p0 = atomicAdd(&G_CUR[d2.x], 1);
    g_srcs[g_off[d2.x] + p0] = s2.x;
    int p1 = atomicAdd(&G_CUR[d2.y], 1);
    g_srcs[g_off[d2.y] + p1] = s2.y;
}

// ---------------- CSR aggregation (bf16 in, fp32 out), 4-edge unroll ---------
// Thread owns one uint4 = 8 bf16 of its node's row. PARTS = D/8.
template <int D, int LOGP>
__global__ void __launch_bounds__(256)
csr_agg_kernel(const __nv_bfloat16* __restrict__ hin, float* __restrict__ agg) {
    GDC_LAUNCH();
    GDC_WAIT();   // g_srcs (scatter) / hin (prev update)
    constexpr int PARTS = 1 << LOGP;          // 4 (D=32) or 8 (D=64)
    int t = blockIdx.x * blockDim.x + threadIdx.x;
    int node = t >> LOGP;
    int part = t & (PARTS - 1);
    if (node >= N_NODES) return;
    int lo = g_off[node];
    int hi = g_off[node + 1];

    float a[8];
#pragma unroll
    for (int j = 0; j < 8; j++) a[j] = 0.0f;

    const uint4* base = (const uint4*)hin + part;  // row = PARTS uint4
    int e = lo;
    for (; e + 4 <= hi; e += 4) {
        int s0 = g_srcs[e];
        int s1 = g_srcs[e + 1];
        int s2 = g_srcs[e + 2];
        int s3 = g_srcs[e + 3];
        uint4 u0 = base[(long)s0 * PARTS];
        uint4 u1 = base[(long)s1 * PARTS];
        uint4 u2 = base[(long)s2 * PARTS];
        uint4 u3 = base[(long)s3 * PARTS];
        a[0] += (bf_lo(u0.x) + bf_lo(u1.x)) + (bf_lo(u2.x) + bf_lo(u3.x));
        a[1] += (bf_hi(u0.x) + bf_hi(u1.x)) + (bf_hi(u2.x) + bf_hi(u3.x));
        a[2] += (bf_lo(u0.y) + bf_lo(u1.y)) + (bf_lo(u2.y) + bf_lo(u3.y));
        a[3] += (bf_hi(u0.y) + bf_hi(u1.y)) + (bf_hi(u2.y) + bf_hi(u3.y));
        a[4] += (bf_lo(u0.z) + bf_lo(u1.z)) + (bf_lo(u2.z) + bf_lo(u3.z));
        a[5] += (bf_hi(u0.z) + bf_hi(u1.z)) + (bf_hi(u2.z) + bf_hi(u3.z));
        a[6] += (bf_lo(u0.w) + bf_lo(u1.w)) + (bf_lo(u2.w) + bf_lo(u3.w));
        a[7] += (bf_hi(u0.w) + bf_hi(u1.w)) + (bf_hi(u2.w) + bf_hi(u3.w));
    }
    for (; e < hi; e++) {
        int s = g_srcs[e];
        uint4 u = base[(long)s * PARTS];
        a[0] += bf_lo(u.x); a[1] += bf_hi(u.x);
        a[2] += bf_lo(u.y); a[3] += bf_hi(u.y);
        a[4] += bf_lo(u.z); a[5] += bf_hi(u.z);
        a[6] += bf_lo(u.w); a[7] += bf_hi(u.w);
    }
    float4* out = (float4*)agg + (long)node * (D / 4) + part * 2;
    out[0] = make_float4(a[0], a[1], a[2], a[3]);
    out[1] = make_float4(a[4], a[5], a[6], a[7]);
}

// ---------------- node update: agg(fp32)@Wrel^T + b + h(bf16)@Wroot^T, relu -
// POOL=true: reduce relu'd rows into G_GSUM[graph]; else write bf16 h rows.
template <int DIN, bool POOL>
__global__ void __launch_bounds__(128)
node_update_kernel(const float* __restrict__ agg,
                   const __nv_bfloat16* __restrict__ hin,
                   const float* __restrict__ Wrel,
                   const float* __restrict__ brel,
                   const float* __restrict__ Wroot,
                   __nv_bfloat16* __restrict__ hout,
                   const int* __restrict__ batch) {
    GDC_LAUNCH();
    __shared__ float sWrel[DIN * 64];
    __shared__ float sWroot[DIN * 64];
    __shared__ float sB[64];
    // weight staging reads only kernel inputs — overlaps predecessor via PDL
    for (int idx = threadIdx.x; idx < DIN * 64; idx += blockDim.x) {
        int o = idx & 63, k = idx >> 6;
        sWrel[idx]  = Wrel[o * DIN + k];
        sWroot[idx] = Wroot[o * DIN + k];
    }
    for (int idx = threadIdx.x; idx < 64; idx += blockDim.x) sB[idx] = brel[idx];
    GDC_WAIT();   // agg from csr_agg
    __syncthreads();

    int t = blockIdx.x * blockDim.x + threadIdx.x;
    int quad = t >> 1;
    int part = t & 1;
    int n0 = quad * 4;
    if (n0 >= N_NODES) return;

    unsigned long long acc[4][16];
#pragma unroll
    for (int p = 0; p < 16; p++) {
        unsigned long long b2 = pack_f32(sB[part * 32 + p * 2], sB[part * 32 + p * 2 + 1]);
#pragma unroll
        for (int n = 0; n < 4; n++) acc[n][p] = b2;
    }

    const float4* aB = (const float4*)(agg + (long)n0 * DIN);
    const uint2* hB = (const uint2*)(hin + (long)n0 * DIN);  // uint2 = 4 bf16
    constexpr int R4 = DIN / 4;

    for (int k4 = 0; k4 < DIN / 4; k4++) {
        float4 av[4], hv[4];
#pragma unroll
        for (int n = 0; n < 4; n++) {
            av[n] = aB[(long)n * R4 + k4];
            uint2 hu = hB[(long)n * R4 + k4];
            hv[n] = make_float4(bf_lo(hu.x), bf_hi(hu.x), bf_lo(hu.y), bf_hi(hu.y));
        }
#pragma unroll
        for (int kk = 0; kk < 4; kk++) {
            int k = k4 * 4 + kk;
            const unsigned long long* wr =
                (const unsigned long long*)(sWrel + k * 64 + part * 32);
            const unsigned long long* wo =
                (const unsigned long long*)(sWroot + k * 64 + part * 32);
            unsigned long long ad[4], hd[4];
#pragma unroll
            for (int n = 0; n < 4; n++) {
                float as = (kk == 0) ? av[n].x : (kk == 1) ? av[n].y : (kk == 2) ? av[n].z : av[n].w;
                float hs = (kk == 0) ? hv[n].x : (kk == 1) ? hv[n].y : (kk == 2) ? hv[n].z : hv[n].w;
                ad[n] = dup_f32(as);
                hd[n] = dup_f32(hs);
            }
#pragma unroll
            for (int p = 0; p < 16; p++) {
                unsigned long long w1 = wr[p];
                unsigned long long w2 = wo[p];
#pragma unroll
                for (int n = 0; n < 4; n++) {
                    fma2(acc[n][p], w1, ad[n]);
                    fma2(acc[n][p], w2, hd[n]);
                }
            }
        }
    }

#pragma unroll
    for (int n = 0; n < 4; n++) {
        float r[32];
#pragma unroll
        for (int j = 0; j < 16; j++) {
            float2 f = unpack_f32(acc[n][j]);
            r[j * 2]     = fmaxf(f.x, 0.f);
            r[j * 2 + 1] = fmaxf(f.y, 0.f);
        }
        if (POOL) {
            int g = batch[n0 + n];
            float* gp = G_GSUM + (long)g * 64 + part * 32;
#pragma unroll
            for (int q = 0; q < 8; q++)
                red_v4(gp + q * 4, r[q * 4], r[q * 4 + 1], r[q * 4 + 2], r[q * 4 + 3]);
        } else {
            unsigned w[16];
#pragma unroll
            for (int j = 0; j < 16; j++) w[j] = bf_pack(r[j * 2], r[j * 2 + 1]);
            uint4* d = (uint4*)(hout + (long)(n0 + n) * 64 + part * 32);
#pragma unroll
            for (int q = 0; q < 4; q++)
                d[q] = make_uint4(w[q * 4], w[q * 4 + 1], w[q * 4 + 2], w[q * 4 + 3]);
        }
    }
}

// ---------------- final: mean + classifier (reads 256KB gsum) ----------------
__global__ void __launch_bounds__(64)
pool_cls_kernel(const float* __restrict__ W_cls,
                const float* __restrict__ b_cls,
                float* __restrict__ out) {
    GDC_WAIT();   // G_GSUM from upd64
    __shared__ float sp[64];
    int g = blockIdx.x;
    int tid = threadIdx.x;
    float cnt = fmaxf((float)(g_goff[g + 1] - g_goff[g]), 1.0f);
    sp[tid] = G_GSUM[(long)g * 64 + tid] / cnt;
    __syncthreads();

    if (tid < 10) {
        float r = b_cls[tid];
#pragma unroll
        for (int k = 0; k < 64; k++) r += sp[k] * W_cls[tid * 64 + k];
        out[(long)g * 10 + tid] = r;
    }
}

// ---------------- PDL launch helper ------------------------------------------
template <typename F, typename... Args>
static inline void launch_pdl(F f, int grid, int block, Args... args) {
    cudaLaunchConfig_t cfg = {};
    cfg.gridDim = dim3(grid, 1, 1);
    cfg.blockDim = dim3(block, 1, 1);
    cfg.dynamicSmemBytes = 0;
    cfg.stream = 0;
    cudaLaunchAttribute at[1];
    at[0].id = cudaLaunchAttributeProgrammaticStreamSerialization;
    at[0].val.programmaticStreamSerializationAllowed = 1;
    cfg.attrs = at;
    cfg.numAttrs = 1;
    cudaLaunchKernelEx(&cfg, f, args...);
}

// ---------------- launch ------------------------------------------------------
extern "C" void kernel_launch(void* const* d_in, const int* in_sizes, int n_in,
                              void* d_out, int out_size) {
    const int* x     = (const int*)d_in[0];
    const int* edge  = (const int*)d_in[1];
    const int* batch = (const int*)d_in[2];

    int se = -1;
    for (int i = 3; i < n_in; i++) {
        if (in_sizes[i] == 128) { se = i; break; }
    }
    if (se < 0) se = (n_in == 16) ? 4 : 3;

    const float* shape_emb = (const float*)d_in[se + 0];
    const float* color_emb = (const float*)d_in[se + 1];
    const float* W_pre     = (const float*)d_in[se + 2];
    const float* b_pre     = (const float*)d_in[se + 3];
    const float* W_rel1    = (const float*)d_in[se + 4];
    const float* b_rel1    = (const float*)d_in[se + 5];
    const float* W_root1   = (const float*)d_in[se + 6];
    const float* W_rel2    = (const float*)d_in[se + 7];
    const float* b_rel2    = (const float*)d_in[se + 8];
    const float* W_root2   = (const float*)d_in[se + 9];
    const float* W_cls     = (const float*)d_in[se + 10];
    const float* b_cls     = (const float*)d_in[se + 11];

    float* out = (float*)d_out;

    void *p_agg1, *p_agg2, *p_h0, *p_h1, *p_zero;
    cudaGetSymbolAddress(&p_agg1, g_agg1);
    cudaGetSymbolAddress(&p_agg2, g_agg2);
    cudaGetSymbolAddress(&p_h0, g_h0);
    cudaGetSymbolAddress(&p_h1, g_h1);
    cudaGetSymbolAddress(&p_zero, g_zero);

    cudaMemsetAsync(p_zero, 0, (size_t)ZERO_INTS * sizeof(int));

    const int* src = edge;
    const int* dstp = edge + N_EDGES;

    // first kernel after memset: plain launch (full dependency on memset)
    hist_embed_kernel<<<EMB_BLOCKS + (N_EDGES + 255) / 256, 256>>>(
        dstp, batch, x, shape_emb, color_emb, W_pre, b_pre);

    launch_pdl(scan_all_kernel, SCAN_BLOCKS + 1, 256);

    launch_pdl(scatter_kernel, (N_EDGES / 2 + 255) / 256, 256, src, dstp);

    {
        long threads = (long)N_NODES * 4;   // PARTS=4 for D=32 (8 bf16/thread)
        launch_pdl(csr_agg_kernel<32, 2>, (int)((threads + 255) / 256), 256,
                   (const __nv_bfloat16*)p_h0, (float*)p_agg1);
    }
    {
        int threads = (N_NODES / 4) * 2;
        launch_pdl(node_update_kernel<32, false>, (threads + 127) / 128, 128,
                   (const float*)p_agg1, (const __nv_bfloat16*)p_h0,
                   W_rel1, b_rel1, W_root1,
                   (__nv_bfloat16*)p_h1, batch);
    }
    {
        long threads = (long)N_NODES * 8;   // PARTS=8 for D=64 (8 bf16/thread)
        launch_pdl(csr_agg_kernel<64, 3>, (int)((threads + 255) / 256), 256,
                   (const __nv_bfloat16*)p_h1, (float*)p_agg2);
    }
    {
        int threads = (N_NODES / 4) * 2;
        launch_pdl(node_update_kernel<64, true>, (threads + 127) / 128, 128,
                   (const float*)p_agg2, (const __nv_bfloat16*)p_h1,
                   W_rel2, b_rel2, W_root2,
                   (__nv_bfloat16*)nullptr, batch);
    }

    launch_pdl(pool_cls_kernel, N_GRAPHS, 64, W_cls, b_cls, out);

    (void)out_size;
}